// round 8
// baseline (speedup 1.0000x reference)
#include <cuda_runtime.h>
#include <math.h>

#define NBATCH  16
#define NATOM   512
#define NEIGH   64
#define NPAIR   (NATOM*NEIGH)        /* 32768  */
#define TOTATOM (NBATCH*NATOM)       /* 8192   */
#define NPTOT   (NBATCH*NPAIR)       /* 524288 */
#define NWAVE   8
#define NL      13
#define NFEAT   104                  /* NL * NWAVE */
#define NORBIT  128
#define GATOMS  16

#define PBLK    64                   /* k_pairs blocks per batch            */
#define PPB     512                  /* pairs per k_pairs block             */
#define SLOT    12                   /* slots per (atom, block) cell        */
#define RCAP    256                  /* SMEM record capacity per atom       */

// d_rec[((b*NATOM + atom)*PBLK + blk)*SLOT + slot] : (dx,dy,dz,species)
__device__ float4        d_rec[(size_t)TOTATOM * PBLK * SLOT];
__device__ unsigned char d_cnt[TOTATOM * PBLK];   // written wholesale each run
__device__ float         d_sw[(size_t)TOTATOM * NFEAT];

// ---------------------------------------------------------------------------
// Kernel 1: displacement + species, binned via SMEM cursors (no global RMW).
// ---------------------------------------------------------------------------
__global__ void __launch_bounds__(256)
k_pairs(const float* __restrict__ cart,
        const int*   __restrict__ species,
        const int*   __restrict__ atom_index,
        const float* __restrict__ shifts)
{
    __shared__ float scart[NATOM * 3];
    __shared__ int   ssp  [NATOM];
    __shared__ int   scur [NATOM];

    const int blk = blockIdx.x;               // 0..63 within batch
    const int b   = blockIdx.y;
    const int tid = threadIdx.x;

    const float* cb = cart + (size_t)b * NATOM * 3;
    for (int i = tid; i < NATOM * 3; i += 256) scart[i] = cb[i];
    for (int i = tid; i < NATOM;     i += 256) {
        ssp[i]  = species[b * NATOM + i];
        scur[i] = 0;
    }
    __syncthreads();

#pragma unroll
    for (int u = 0; u < 2; ++u) {
        const int p_loc = blk * PPB + u * 256 + tid;
        const int p     = b * NPAIR + p_loc;

        const int i_loc = atom_index[p];
        const int j_loc = atom_index[NPTOT + p];

        float dx = scart[3*i_loc+0] - scart[3*j_loc+0] + shifts[3*p+0];
        float dy = scart[3*i_loc+1] - scart[3*j_loc+1] + shifts[3*p+1];
        float dz = scart[3*i_loc+2] - scart[3*j_loc+2] + shifts[3*p+2];

        int pos = atomicAdd(&scur[i_loc], 1);     // SMEM atomic
        if (pos < SLOT)
            d_rec[(((size_t)(b * NATOM + i_loc)) * PBLK + blk) * SLOT + pos] =
                make_float4(dx, dy, dz, __int_as_float(ssp[j_loc]));
    }
    __syncthreads();

    for (int i = tid; i < NATOM; i += 256) {
        int c = scur[i];
        d_cnt[(b * NATOM + i) * PBLK + blk] =
            (unsigned char)(c < SLOT ? c : SLOT);
    }
}

// ---------------------------------------------------------------------------
// Kernel 2a: block per atom -> sw[13][8].
// Counts: 64 uchars (2 sectors) + 2-warp scan. Gather: 2 lanes/cell parallel
// pass (c<=2 covers ~92%) + serial remainder. Then phases A/B + shuffle red.
// ---------------------------------------------------------------------------
__global__ void __launch_bounds__(128)
k_accum(const float* __restrict__ rs,
        const float* __restrict__ inta,
        const float* __restrict__ params,
        const float* __restrict__ cutoff,
        float*       __restrict__ swout)
{
    __shared__ float4 recs[RCAP];
    __shared__ float2 dfc [RCAP];
    __shared__ float  stab[96];       // [0:32) rs, [32:64) inta, [64:96) params
    __shared__ float  red [NL * NWAVE * 4];
    __shared__ int    scnt[PBLK], soff[PBLK], swtot[2];

    const int atom = blockIdx.x;
    const int t    = threadIdx.x;
    const int warp = t >> 5;
    const int lane = t & 31;

    const float4* src = &d_rec[(size_t)atom * PBLK * SLOT];

    if (t < 32) {
        stab[t]      = rs[t];
        stab[32 + t] = inta[t];
        stab[64 + t] = params[t];
    }
    if (t < PBLK) {                               // warps 0,1: counts + scan
        int c = (int)d_cnt[atom * PBLK + t];
        scnt[t] = c;
        int x = c;
#pragma unroll
        for (int dd = 1; dd < 32; dd <<= 1) {
            int y = __shfl_up_sync(0xffffffffu, x, dd);
            if (lane >= dd) x += y;
        }
        soff[t] = x - c;
        if (lane == 31) swtot[warp] = x;
    }
    __syncthreads();

    const int half = swtot[0];
    const int n0   = half + swtot[1];
    const int n    = n0 < RCAP ? n0 : RCAP;

    // parallel pass: 2 lanes per cell cover slots 0..1 of all 64 cells
    {
        const int r = t >> 1;
        const int s = t & 1;
        if (s < scnt[r])
            recs[soff[r] + (r >= 32 ? half : 0) + s] = src[r * SLOT + s];
    }
    // remainder: slots 2..c-1 (rare), one lane per cell
    if (t < PBLK) {
        const int c    = scnt[t];
        const int base = soff[t] + (t >= 32 ? half : 0);
        for (int s = 2; s < c; ++s)
            recs[base + s] = src[t * SLOT + s];
    }
    __syncthreads();

    // Phase A: per-pair distance + cutoff
    const float icp = 3.14159265358979323846f / cutoff[0];
    for (int p = t; p < n; p += 128) {
        float4 v = recs[p];
        float d  = sqrtf(v.x*v.x + v.y*v.y + v.z*v.z);
        float c  = 0.5f * __cosf(d * icp) + 0.5f;
        dfc[p]   = make_float2(d, c * c);
    }
    __syncthreads();

    // Phase B: thread = (w = t&7, slice = t>>3)
    const int w  = t & 7;
    const int sl = t >> 3;

    float acc[NL];
#pragma unroll
    for (int l = 0; l < NL; ++l) acc[l] = 0.f;

    for (int p = sl; p < n; p += 16) {
        float4 v  = recs[p];
        float2 df = dfc[p];
        int   sp  = __float_as_int(v.w);
        float tt  = df.x - stab[sp*8 + w];
        float r   = stab[64 + sp*8 + w] * __expf(stab[32 + sp*8 + w] * tt * tt);
        float q   = df.y * r;
        float qx = q * v.x, qy = q * v.y, qz = q * v.z;
        acc[0]  += q;
        acc[1]  += qx;        acc[2]  += qy;        acc[3]  += qz;
        acc[4]  += qx * v.x;  acc[5]  += qx * v.y;  acc[6]  += qx * v.z;
        acc[7]  += qy * v.x;  acc[8]  += qy * v.y;  acc[9]  += qy * v.z;
        acc[10] += qz * v.x;  acc[11] += qz * v.y;  acc[12] += qz * v.z;
    }

#pragma unroll
    for (int l = 0; l < NL; ++l) {
        acc[l] += __shfl_xor_sync(0xffffffffu, acc[l], 8);
        acc[l] += __shfl_xor_sync(0xffffffffu, acc[l], 16);
    }
    if (lane < 8) {
#pragma unroll
        for (int l = 0; l < NL; ++l)
            red[(l * NWAVE + lane) * 4 + warp] = acc[l];
    }
    __syncthreads();

    if (t < NFEAT) {
        float4 v = *reinterpret_cast<const float4*>(&red[t * 4]);
        swout[(size_t)atom * NFEAT + t] = (v.x + v.y) + (v.z + v.w);
    }
}

// ---------------------------------------------------------------------------
// Kernel 2b: density[atom][m] = sum_l ( sum_w sw[l][w]*hp[l][w][m] )^2
// ---------------------------------------------------------------------------
__global__ void __launch_bounds__(128)
k_stage2(const float* __restrict__ hyper,      // (3, 8, 128)
         const int*   __restrict__ index_para, // (13,)
         const float* __restrict__ sw,         // (8192, 104)
         float*       __restrict__ out)        // (8192, 128)
{
    const int t = threadIdx.x;

    float hp[NFEAT];
#pragma unroll
    for (int l = 0; l < NL; ++l) {
        int ip = index_para[l];
#pragma unroll
        for (int w = 0; w < NWAVE; ++w)
            hp[l*NWAVE + w] = hyper[(ip*NWAVE + w)*NORBIT + t];
    }

    __shared__ float swsm[GATOMS * NFEAT];
    const int base = blockIdx.x * GATOMS;

    for (int i = t; i < GATOMS * NFEAT; i += 128)
        swsm[i] = sw[(size_t)base * NFEAT + i];
    __syncthreads();

#pragma unroll 2
    for (int g = 0; g < GATOMS; ++g) {
        const float4* s4 = reinterpret_cast<const float4*>(&swsm[g * NFEAT]);
        float dens = 0.f;
#pragma unroll
        for (int l = 0; l < NL; ++l) {
            float4 a = s4[l*2], bb = s4[l*2+1];
            float h = a.x*hp[l*8+0] + a.y*hp[l*8+1] + a.z*hp[l*8+2] + a.w*hp[l*8+3]
                    + bb.x*hp[l*8+4] + bb.y*hp[l*8+5] + bb.z*hp[l*8+6] + bb.w*hp[l*8+7];
            dens += h * h;
        }
        out[(size_t)(base + g)*NORBIT + t] = dens;
    }
}

// ---------------------------------------------------------------------------
extern "C" void kernel_launch(void* const* d_in, const int* in_sizes, int n_in,
                              void* d_out, int out_size)
{
    const float* cart    = (const float*)d_in[0];
    const int*   species = (const int*)  d_in[2];
    const int*   aidx    = (const int*)  d_in[3];
    const float* shifts  = (const float*)d_in[4];
    const float* rs      = (const float*)d_in[5];
    const float* inta    = (const float*)d_in[6];
    const float* params  = (const float*)d_in[7];
    const float* hyper   = (const float*)d_in[8];
    const int*   ipara   = (const int*)  d_in[9];
    const float* cutoff  = (const float*)d_in[10];
    float*       out     = (float*)d_out;

    void* swp = nullptr;
    cudaGetSymbolAddress(&swp, d_sw);

    dim3 pgrid(PBLK, NBATCH);
    k_pairs<<<pgrid, 256>>>(cart, species, aidx, shifts);
    k_accum<<<TOTATOM, 128>>>(rs, inta, params, cutoff, (float*)swp);
    k_stage2<<<TOTATOM / GATOMS, 128>>>(hyper, ipara, (const float*)swp, out);
}

// round 9
// speedup vs baseline: 1.0478x; 1.0478x over previous
#include <cuda_runtime.h>
#include <math.h>

#define NBATCH  16
#define NATOM   512
#define NEIGH   64
#define NPAIR   (NATOM*NEIGH)        /* 32768  */
#define TOTATOM (NBATCH*NATOM)       /* 8192   */
#define NPTOT   (NBATCH*NPAIR)       /* 524288 */
#define NWAVE   8
#define NL      13
#define NFEAT   104                  /* NL * NWAVE */
#define NORBIT  128
#define GATOMS  16

#define PBLK    32                   /* k_pairs blocks per batch            */
#define PPB     1024                 /* pairs per k_pairs block             */
#define SLOT    16                   /* slots per (atom, block) cell        */
#define RCAP    512                  /* SMEM record capacity per atom       */

// d_rec[((b*NATOM + atom)*PBLK + blk)*SLOT + slot] : (dx,dy,dz,species)
__device__ float4        d_rec[(size_t)TOTATOM * PBLK * SLOT];
__device__ unsigned char d_cnt[TOTATOM * PBLK];   // written wholesale each run
__device__ float         d_sw[(size_t)TOTATOM * NFEAT];

// ---------------------------------------------------------------------------
// Kernel 1: displacement + species, binned via SMEM cursors (no global RMW).
// ---------------------------------------------------------------------------
__global__ void __launch_bounds__(256)
k_pairs(const float* __restrict__ cart,
        const int*   __restrict__ species,
        const int*   __restrict__ atom_index,
        const float* __restrict__ shifts)
{
    __shared__ float scart[NATOM * 3];
    __shared__ int   ssp  [NATOM];
    __shared__ int   scur [NATOM];

    const int blk = blockIdx.x;               // 0..31 within batch
    const int b   = blockIdx.y;
    const int tid = threadIdx.x;

    const float* cb = cart + (size_t)b * NATOM * 3;
    for (int i = tid; i < NATOM * 3; i += 256) scart[i] = cb[i];
    for (int i = tid; i < NATOM;     i += 256) {
        ssp[i]  = species[b * NATOM + i];
        scur[i] = 0;
    }
    __syncthreads();

#pragma unroll
    for (int u = 0; u < 4; ++u) {
        const int p_loc = blk * PPB + u * 256 + tid;
        const int p     = b * NPAIR + p_loc;

        const int i_loc = atom_index[p];
        const int j_loc = atom_index[NPTOT + p];

        float dx = scart[3*i_loc+0] - scart[3*j_loc+0] + shifts[3*p+0];
        float dy = scart[3*i_loc+1] - scart[3*j_loc+1] + shifts[3*p+1];
        float dz = scart[3*i_loc+2] - scart[3*j_loc+2] + shifts[3*p+2];

        int pos = atomicAdd(&scur[i_loc], 1);     // SMEM atomic
        if (pos < SLOT)
            d_rec[(((size_t)(b * NATOM + i_loc)) * PBLK + blk) * SLOT + pos] =
                make_float4(dx, dy, dz, __int_as_float(ssp[j_loc]));
    }
    __syncthreads();

    for (int i = tid; i < NATOM; i += 256) {
        int c = scur[i];
        d_cnt[(b * NATOM + i) * PBLK + blk] =
            (unsigned char)(c < SLOT ? c : SLOT);
    }
}

// ---------------------------------------------------------------------------
// Kernel 2a: block per atom -> sw[13][8].
// Counts: 32 uchars = ONE sector + single-warp scan. Gather: 4 lanes/cell
// parallel pass + rare serial remainder. Then phases A/B + shuffle reduction.
// ---------------------------------------------------------------------------
__global__ void __launch_bounds__(128)
k_accum(const float* __restrict__ rs,
        const float* __restrict__ inta,
        const float* __restrict__ params,
        const float* __restrict__ cutoff,
        float*       __restrict__ swout)
{
    __shared__ float4 recs[RCAP];
    __shared__ float2 dfc [RCAP];
    __shared__ float  stab[96];       // [0:32) rs, [32:64) inta, [64:96) params
    __shared__ float  red [NL * NWAVE * 4];
    __shared__ int    scnt[PBLK], soff[PBLK], stot;

    const int atom = blockIdx.x;
    const int t    = threadIdx.x;
    const int warp = t >> 5;
    const int lane = t & 31;

    const float4* src = &d_rec[(size_t)atom * PBLK * SLOT];

    if (t < 32) {
        stab[t]      = rs[t];
        stab[32 + t] = inta[t];
        stab[64 + t] = params[t];
        int c = (int)d_cnt[atom * PBLK + t];      // 32 uchars: 1 sector
        scnt[t] = c;
        int x = c;
#pragma unroll
        for (int dd = 1; dd < 32; dd <<= 1) {
            int y = __shfl_up_sync(0xffffffffu, x, dd);
            if (lane >= dd) x += y;
        }
        soff[t] = x - c;
        if (t == 31) stot = x;
    }
    __syncthreads();

    const int n = stot;

    // parallel pass: 4 lanes per cell cover slots 0..3 of all 32 cells
    {
        const int r = t >> 2;                     // cell 0..31
        const int s = t & 3;                      // slot 0..3
        if (s < scnt[r])
            recs[soff[r] + s] = src[r * SLOT + s];
    }
    // remainder: slots 4..c-1 (rare), one lane per cell
    if (t < PBLK) {
        const int c = scnt[t];
        for (int s = 4; s < c; ++s)
            recs[soff[t] + s] = src[t * SLOT + s];
    }
    __syncthreads();

    // Phase A: per-pair distance + cutoff
    const float icp = 3.14159265358979323846f / cutoff[0];
    for (int p = t; p < n; p += 128) {
        float4 v = recs[p];
        float d  = sqrtf(v.x*v.x + v.y*v.y + v.z*v.z);
        float c  = 0.5f * __cosf(d * icp) + 0.5f;
        dfc[p]   = make_float2(d, c * c);
    }
    __syncthreads();

    // Phase B: thread = (w = t&7, slice = t>>3)
    const int w  = t & 7;
    const int sl = t >> 3;

    float acc[NL];
#pragma unroll
    for (int l = 0; l < NL; ++l) acc[l] = 0.f;

    for (int p = sl; p < n; p += 16) {
        float4 v  = recs[p];
        float2 df = dfc[p];
        int   sp  = __float_as_int(v.w);
        float tt  = df.x - stab[sp*8 + w];
        float r   = stab[64 + sp*8 + w] * __expf(stab[32 + sp*8 + w] * tt * tt);
        float q   = df.y * r;
        float qx = q * v.x, qy = q * v.y, qz = q * v.z;
        acc[0]  += q;
        acc[1]  += qx;        acc[2]  += qy;        acc[3]  += qz;
        acc[4]  += qx * v.x;  acc[5]  += qx * v.y;  acc[6]  += qx * v.z;
        acc[7]  += qy * v.x;  acc[8]  += qy * v.y;  acc[9]  += qy * v.z;
        acc[10] += qz * v.x;  acc[11] += qz * v.y;  acc[12] += qz * v.z;
    }

#pragma unroll
    for (int l = 0; l < NL; ++l) {
        acc[l] += __shfl_xor_sync(0xffffffffu, acc[l], 8);
        acc[l] += __shfl_xor_sync(0xffffffffu, acc[l], 16);
    }
    if (lane < 8) {
#pragma unroll
        for (int l = 0; l < NL; ++l)
            red[(l * NWAVE + lane) * 4 + warp] = acc[l];
    }
    __syncthreads();

    if (t < NFEAT) {
        float4 v = *reinterpret_cast<const float4*>(&red[t * 4]);
        swout[(size_t)atom * NFEAT + t] = (v.x + v.y) + (v.z + v.w);
    }
}

// ---------------------------------------------------------------------------
// Kernel 2b: density[atom][m] = sum_l ( sum_w sw[l][w]*hp[l][w][m] )^2
// ---------------------------------------------------------------------------
__global__ void __launch_bounds__(128)
k_stage2(const float* __restrict__ hyper,      // (3, 8, 128)
         const int*   __restrict__ index_para, // (13,)
         const float* __restrict__ sw,         // (8192, 104)
         float*       __restrict__ out)        // (8192, 128)
{
    const int t = threadIdx.x;

    float hp[NFEAT];
#pragma unroll
    for (int l = 0; l < NL; ++l) {
        int ip = index_para[l];
#pragma unroll
        for (int w = 0; w < NWAVE; ++w)
            hp[l*NWAVE + w] = hyper[(ip*NWAVE + w)*NORBIT + t];
    }

    __shared__ float swsm[GATOMS * NFEAT];
    const int base = blockIdx.x * GATOMS;

    for (int i = t; i < GATOMS * NFEAT; i += 128)
        swsm[i] = sw[(size_t)base * NFEAT + i];
    __syncthreads();

#pragma unroll 2
    for (int g = 0; g < GATOMS; ++g) {
        const float4* s4 = reinterpret_cast<const float4*>(&swsm[g * NFEAT]);
        float dens = 0.f;
#pragma unroll
        for (int l = 0; l < NL; ++l) {
            float4 a = s4[l*2], bb = s4[l*2+1];
            float h = a.x*hp[l*8+0] + a.y*hp[l*8+1] + a.z*hp[l*8+2] + a.w*hp[l*8+3]
                    + bb.x*hp[l*8+4] + bb.y*hp[l*8+5] + bb.z*hp[l*8+6] + bb.w*hp[l*8+7];
            dens += h * h;
        }
        out[(size_t)(base + g)*NORBIT + t] = dens;
    }
}

// ---------------------------------------------------------------------------
extern "C" void kernel_launch(void* const* d_in, const int* in_sizes, int n_in,
                              void* d_out, int out_size)
{
    const float* cart    = (const float*)d_in[0];
    const int*   species = (const int*)  d_in[2];
    const int*   aidx    = (const int*)  d_in[3];
    const float* shifts  = (const float*)d_in[4];
    const float* rs      = (const float*)d_in[5];
    const float* inta    = (const float*)d_in[6];
    const float* params  = (const float*)d_in[7];
    const float* hyper   = (const float*)d_in[8];
    const int*   ipara   = (const int*)  d_in[9];
    const float* cutoff  = (const float*)d_in[10];
    float*       out     = (float*)d_out;

    void* swp = nullptr;
    cudaGetSymbolAddress(&swp, d_sw);

    dim3 pgrid(PBLK, NBATCH);
    k_pairs<<<pgrid, 256>>>(cart, species, aidx, shifts);
    k_accum<<<TOTATOM, 128>>>(rs, inta, params, cutoff, (float*)swp);
    k_stage2<<<TOTATOM / GATOMS, 128>>>(hyper, ipara, (const float*)swp, out);
}

// round 10
// speedup vs baseline: 1.1108x; 1.0601x over previous
#include <cuda_runtime.h>
#include <math.h>

#define NBATCH  16
#define NATOM   512
#define NEIGH   64
#define NPAIR   (NATOM*NEIGH)        /* 32768  */
#define TOTATOM (NBATCH*NATOM)       /* 8192   */
#define NPTOT   (NBATCH*NPAIR)       /* 524288 */
#define NWAVE   8
#define NL      13
#define NFEAT   104                  /* NL * NWAVE */
#define NORBIT  128
#define GATOMS  16

#define PBLK    32                   /* k_pairs blocks per batch            */
#define PPB     1024                 /* pairs per k_pairs block             */
#define SLOT    16                   /* slots per (atom, block) cell        */
#define RCAP    128                  /* SMEM record capacity per atom (8 sigma) */
#define AW      8                    /* atoms (warps) per k_accum block     */

// d_rec[((b*NATOM + atom)*PBLK + blk)*SLOT + slot] : (dx,dy,dz,species)
__device__ float4        d_rec[(size_t)TOTATOM * PBLK * SLOT];
__device__ unsigned char d_cnt[TOTATOM * PBLK];   // written wholesale each run
__device__ float         d_sw[(size_t)TOTATOM * NFEAT];

// ---------------------------------------------------------------------------
// Kernel 1: displacement + species, binned via SMEM cursors (no global RMW).
// ---------------------------------------------------------------------------
__global__ void __launch_bounds__(256)
k_pairs(const float* __restrict__ cart,
        const int*   __restrict__ species,
        const int*   __restrict__ atom_index,
        const float* __restrict__ shifts)
{
    __shared__ float scart[NATOM * 3];
    __shared__ int   ssp  [NATOM];
    __shared__ int   scur [NATOM];

    const int blk = blockIdx.x;               // 0..31 within batch
    const int b   = blockIdx.y;
    const int tid = threadIdx.x;

    const float* cb = cart + (size_t)b * NATOM * 3;
    for (int i = tid; i < NATOM * 3; i += 256) scart[i] = cb[i];
    for (int i = tid; i < NATOM;     i += 256) {
        ssp[i]  = species[b * NATOM + i];
        scur[i] = 0;
    }
    __syncthreads();

#pragma unroll
    for (int u = 0; u < 4; ++u) {
        const int p_loc = blk * PPB + u * 256 + tid;
        const int p     = b * NPAIR + p_loc;

        const int i_loc = atom_index[p];
        const int j_loc = atom_index[NPTOT + p];

        float dx = scart[3*i_loc+0] - scart[3*j_loc+0] + shifts[3*p+0];
        float dy = scart[3*i_loc+1] - scart[3*j_loc+1] + shifts[3*p+1];
        float dz = scart[3*i_loc+2] - scart[3*j_loc+2] + shifts[3*p+2];

        int pos = atomicAdd(&scur[i_loc], 1);     // SMEM atomic
        if (pos < SLOT)
            d_rec[(((size_t)(b * NATOM + i_loc)) * PBLK + blk) * SLOT + pos] =
                make_float4(dx, dy, dz, __int_as_float(ssp[j_loc]));
    }
    __syncthreads();

    for (int i = tid; i < NATOM; i += 256) {
        int c = scur[i];
        d_cnt[(b * NATOM + i) * PBLK + blk] =
            (unsigned char)(c < SLOT ? c : SLOT);
    }
}

// ---------------------------------------------------------------------------
// Kernel 2a: WARP per atom -> sw[13][8]. 8 atoms per 256-thread block.
// All coordination warp-local (shfl scan, syncwarp); one block barrier total.
// ---------------------------------------------------------------------------
__global__ void __launch_bounds__(256)
k_accum(const float* __restrict__ rs,
        const float* __restrict__ inta,
        const float* __restrict__ params,
        const float* __restrict__ cutoff,
        float*       __restrict__ swout)
{
    __shared__ float4 recs[AW][RCAP];
    __shared__ float2 dfc [AW][RCAP];
    __shared__ float  stab[96];       // [0:32) rs, [32:64) inta, [64:96) params

    const int t    = threadIdx.x;
    const int warp = t >> 5;
    const int lane = t & 31;
    const int atom = blockIdx.x * AW + warp;

    if (t < 32) {
        stab[t]      = rs[t];
        stab[32 + t] = inta[t];
        stab[64 + t] = params[t];
    }
    __syncthreads();                              // the only block barrier

    const float4* src = &d_rec[(size_t)atom * PBLK * SLOT];

    // counts + exclusive scan (lane = cell)
    int c = (int)d_cnt[atom * PBLK + lane];       // 32 uchars: 1 sector
    int x = c;
#pragma unroll
    for (int dd = 1; dd < 32; dd <<= 1) {
        int y = __shfl_up_sync(0xffffffffu, x, dd);
        if (lane >= dd) x += y;
    }
    const int off  = x - c;
    const int ntot = __shfl_sync(0xffffffffu, x, 31);
    const int n    = ntot < RCAP ? ntot : RCAP;

    // gather, parallel pass: 4 lanes per cell, 8 cells per iteration
#pragma unroll
    for (int it = 0; it < 4; ++it) {
        const int r  = it * 8 + (lane >> 2);
        const int s  = lane & 3;
        const int cr = __shfl_sync(0xffffffffu, c,   r);
        const int orr= __shfl_sync(0xffffffffu, off, r);
        if (s < cr && orr + s < RCAP)
            recs[warp][orr + s] = src[r * SLOT + s];
    }
    // remainder: slots 4..c-1 (rare), lane = cell
    for (int s = 4; s < c; ++s)
        if (off + s < RCAP)
            recs[warp][off + s] = src[lane * SLOT + s];
    __syncwarp();

    // Phase A: per-pair distance + cutoff
    const float icp = 3.14159265358979323846f / cutoff[0];
    for (int p = lane; p < n; p += 32) {
        float4 v = recs[warp][p];
        float d  = sqrtf(v.x*v.x + v.y*v.y + v.z*v.z);
        float cc = 0.5f * __cosf(d * icp) + 0.5f;
        dfc[warp][p] = make_float2(d, cc * cc);
    }
    __syncwarp();

    // Phase B: lane = (w = lane&7, slice = lane>>3 in 0..3)
    const int w  = lane & 7;
    const int sl = lane >> 3;

    float acc[NL];
#pragma unroll
    for (int l = 0; l < NL; ++l) acc[l] = 0.f;

    for (int p = sl; p < n; p += 4) {
        float4 v  = recs[warp][p];
        float2 df = dfc[warp][p];
        int   sp  = __float_as_int(v.w);
        float tt  = df.x - stab[sp*8 + w];
        float r   = stab[64 + sp*8 + w] * __expf(stab[32 + sp*8 + w] * tt * tt);
        float q   = df.y * r;
        float qx = q * v.x, qy = q * v.y, qz = q * v.z;
        acc[0]  += q;
        acc[1]  += qx;        acc[2]  += qy;        acc[3]  += qz;
        acc[4]  += qx * v.x;  acc[5]  += qx * v.y;  acc[6]  += qx * v.z;
        acc[7]  += qy * v.x;  acc[8]  += qy * v.y;  acc[9]  += qy * v.z;
        acc[10] += qz * v.x;  acc[11] += qz * v.y;  acc[12] += qz * v.z;
    }

    // reduce over 4 slices (lanes w, w+8, w+16, w+24)
#pragma unroll
    for (int l = 0; l < NL; ++l) {
        acc[l] += __shfl_xor_sync(0xffffffffu, acc[l], 8);
        acc[l] += __shfl_xor_sync(0xffffffffu, acc[l], 16);
    }

    if (lane < 8) {
        float* dst = &swout[(size_t)atom * NFEAT];
#pragma unroll
        for (int l = 0; l < NL; ++l)
            dst[l * NWAVE + lane] = acc[l];
    }
}

// ---------------------------------------------------------------------------
// Kernel 2b: density[atom][m] = sum_l ( sum_w sw[l][w]*hp[l][w][m] )^2
// ---------------------------------------------------------------------------
__global__ void __launch_bounds__(128)
k_stage2(const float* __restrict__ hyper,      // (3, 8, 128)
         const int*   __restrict__ index_para, // (13,)
         const float* __restrict__ sw,         // (8192, 104)
         float*       __restrict__ out)        // (8192, 128)
{
    const int t = threadIdx.x;

    float hp[NFEAT];
#pragma unroll
    for (int l = 0; l < NL; ++l) {
        int ip = index_para[l];
#pragma unroll
        for (int w = 0; w < NWAVE; ++w)
            hp[l*NWAVE + w] = hyper[(ip*NWAVE + w)*NORBIT + t];
    }

    __shared__ float swsm[GATOMS * NFEAT];
    const int base = blockIdx.x * GATOMS;

    for (int i = t; i < GATOMS * NFEAT; i += 128)
        swsm[i] = sw[(size_t)base * NFEAT + i];
    __syncthreads();

#pragma unroll 2
    for (int g = 0; g < GATOMS; ++g) {
        const float4* s4 = reinterpret_cast<const float4*>(&swsm[g * NFEAT]);
        float dens = 0.f;
#pragma unroll
        for (int l = 0; l < NL; ++l) {
            float4 a = s4[l*2], bb = s4[l*2+1];
            float h = a.x*hp[l*8+0] + a.y*hp[l*8+1] + a.z*hp[l*8+2] + a.w*hp[l*8+3]
                    + bb.x*hp[l*8+4] + bb.y*hp[l*8+5] + bb.z*hp[l*8+6] + bb.w*hp[l*8+7];
            dens += h * h;
        }
        out[(size_t)(base + g)*NORBIT + t] = dens;
    }
}

// ---------------------------------------------------------------------------
extern "C" void kernel_launch(void* const* d_in, const int* in_sizes, int n_in,
                              void* d_out, int out_size)
{
    const float* cart    = (const float*)d_in[0];
    const int*   species = (const int*)  d_in[2];
    const int*   aidx    = (const int*)  d_in[3];
    const float* shifts  = (const float*)d_in[4];
    const float* rs      = (const float*)d_in[5];
    const float* inta    = (const float*)d_in[6];
    const float* params  = (const float*)d_in[7];
    const float* hyper   = (const float*)d_in[8];
    const int*   ipara   = (const int*)  d_in[9];
    const float* cutoff  = (const float*)d_in[10];
    float*       out     = (float*)d_out;

    void* swp = nullptr;
    cudaGetSymbolAddress(&swp, d_sw);

    dim3 pgrid(PBLK, NBATCH);
    k_pairs<<<pgrid, 256>>>(cart, species, aidx, shifts);
    k_accum<<<TOTATOM / AW, 256>>>(rs, inta, params, cutoff, (float*)swp);
    k_stage2<<<TOTATOM / GATOMS, 128>>>(hyper, ipara, (const float*)swp, out);
}

// round 11
// speedup vs baseline: 1.2714x; 1.1446x over previous
#include <cuda_runtime.h>
#include <math.h>

#define NBATCH  16
#define NATOM   512
#define NEIGH   64
#define NPAIR   (NATOM*NEIGH)        /* 32768  */
#define TOTATOM (NBATCH*NATOM)       /* 8192   */
#define NPTOT   (NBATCH*NPAIR)       /* 524288 */
#define NWAVE   8
#define NL      13
#define NORBIT  128
#define GATOMS  16
#define SWLEN   68                   /* s0[8] + s1[24] + U2[36] */

#define PBLK    32                   /* k_pairs blocks per batch            */
#define PPB     1024                 /* pairs per k_pairs block             */
#define SLOT    16                   /* slots per (atom, block) cell        */
#define RCAP    128                  /* SMEM record capacity per atom       */
#define AW      8                    /* atoms (warps) per k_accum block     */

// d_rec[((b*NATOM + atom)*PBLK + blk)*SLOT + slot] : (dx,dy,dz,species)
__device__ float4        d_rec[(size_t)TOTATOM * PBLK * SLOT];
__device__ unsigned char d_cnt[TOTATOM * PBLK];   // written wholesale each run
__device__ float         d_sw[(size_t)TOTATOM * SWLEN];

// ---------------------------------------------------------------------------
// Kernel 1: displacement + species, binned via SMEM cursors (no global RMW).
// ---------------------------------------------------------------------------
__global__ void __launch_bounds__(256)
k_pairs(const float* __restrict__ cart,
        const int*   __restrict__ species,
        const int*   __restrict__ atom_index,
        const float* __restrict__ shifts)
{
    __shared__ float scart[NATOM * 3];
    __shared__ int   ssp  [NATOM];
    __shared__ int   scur [NATOM];

    const int blk = blockIdx.x;               // 0..31 within batch
    const int b   = blockIdx.y;
    const int tid = threadIdx.x;

    const float* cb = cart + (size_t)b * NATOM * 3;
    for (int i = tid; i < NATOM * 3; i += 256) scart[i] = cb[i];
    for (int i = tid; i < NATOM;     i += 256) {
        ssp[i]  = species[b * NATOM + i];
        scur[i] = 0;
    }
    __syncthreads();

#pragma unroll
    for (int u = 0; u < 4; ++u) {
        const int p_loc = blk * PPB + u * 256 + tid;
        const int p     = b * NPAIR + p_loc;

        const int i_loc = atom_index[p];
        const int j_loc = atom_index[NPTOT + p];

        float dx = scart[3*i_loc+0] - scart[3*j_loc+0] + shifts[3*p+0];
        float dy = scart[3*i_loc+1] - scart[3*j_loc+1] + shifts[3*p+1];
        float dz = scart[3*i_loc+2] - scart[3*j_loc+2] + shifts[3*p+2];

        int pos = atomicAdd(&scur[i_loc], 1);     // SMEM atomic
        if (pos < SLOT)
            d_rec[(((size_t)(b * NATOM + i_loc)) * PBLK + blk) * SLOT + pos] =
                make_float4(dx, dy, dz, __int_as_float(ssp[j_loc]));
    }
    __syncthreads();

    for (int i = tid; i < NATOM; i += 256) {
        int c = scur[i];
        d_cnt[(b * NATOM + i) * PBLK + blk] =
            (unsigned char)(c < SLOT ? c : SLOT);
    }
}

// ---------------------------------------------------------------------------
// Kernel 2a: WARP per atom. Emits per-atom descriptor:
//   [0:8)   s0[w]            (l = 0 row)
//   [8:32)  s1[l-1][w]       (l = 1..3 rows)
//   [32:68) U2[tri(w,w')]    Gram of l = 4..12 rows, off-diag pre-scaled x2
// ---------------------------------------------------------------------------
__global__ void __launch_bounds__(256)
k_accum(const float* __restrict__ rs,
        const float* __restrict__ inta,
        const float* __restrict__ params,
        const float* __restrict__ cutoff,
        float*       __restrict__ swout)
{
    __shared__ float4 recs[AW][RCAP];
    __shared__ float2 dfc [AW][RCAP];
    __shared__ float  stab[96];       // [0:32) rs, [32:64) inta, [64:96) params

    const int t    = threadIdx.x;
    const int warp = t >> 5;
    const int lane = t & 31;
    const int atom = blockIdx.x * AW + warp;

    if (t < 32) {
        stab[t]      = rs[t];
        stab[32 + t] = inta[t];
        stab[64 + t] = params[t];
    }
    __syncthreads();                              // the only block barrier

    const float4* src = &d_rec[(size_t)atom * PBLK * SLOT];

    // counts + exclusive scan (lane = cell)
    int c = (int)d_cnt[atom * PBLK + lane];       // 32 uchars: 1 sector
    int x = c;
#pragma unroll
    for (int dd = 1; dd < 32; dd <<= 1) {
        int y = __shfl_up_sync(0xffffffffu, x, dd);
        if (lane >= dd) x += y;
    }
    const int off  = x - c;
    const int ntot = __shfl_sync(0xffffffffu, x, 31);
    const int n    = ntot < RCAP ? ntot : RCAP;

    // gather, parallel pass: 4 lanes per cell, 8 cells per iteration
#pragma unroll
    for (int it = 0; it < 4; ++it) {
        const int r  = it * 8 + (lane >> 2);
        const int s  = lane & 3;
        const int cr = __shfl_sync(0xffffffffu, c,   r);
        const int orr= __shfl_sync(0xffffffffu, off, r);
        if (s < cr && orr + s < RCAP)
            recs[warp][orr + s] = src[r * SLOT + s];
    }
    for (int s = 4; s < c; ++s)                   // rare remainder
        if (off + s < RCAP)
            recs[warp][off + s] = src[lane * SLOT + s];
    __syncwarp();

    // Phase A: per-pair distance + cutoff
    const float icp = 3.14159265358979323846f / cutoff[0];
    for (int p = lane; p < n; p += 32) {
        float4 v = recs[warp][p];
        float d  = sqrtf(v.x*v.x + v.y*v.y + v.z*v.z);
        float cc = 0.5f * __cosf(d * icp) + 0.5f;
        dfc[warp][p] = make_float2(d, cc * cc);
    }
    __syncwarp();

    // Phase B: lane = (w = lane&7, slice = lane>>3 in 0..3)
    const int w  = lane & 7;
    const int sl = lane >> 3;

    float acc[NL];
#pragma unroll
    for (int l = 0; l < NL; ++l) acc[l] = 0.f;

    for (int p = sl; p < n; p += 4) {
        float4 v  = recs[warp][p];
        float2 df = dfc[warp][p];
        int   sp  = __float_as_int(v.w);
        float tt  = df.x - stab[sp*8 + w];
        float r   = stab[64 + sp*8 + w] * __expf(stab[32 + sp*8 + w] * tt * tt);
        float q   = df.y * r;
        float qx = q * v.x, qy = q * v.y, qz = q * v.z;
        acc[0]  += q;
        acc[1]  += qx;        acc[2]  += qy;        acc[3]  += qz;
        acc[4]  += qx * v.x;  acc[5]  += qx * v.y;  acc[6]  += qx * v.z;
        acc[7]  += qy * v.x;  acc[8]  += qy * v.y;  acc[9]  += qy * v.z;
        acc[10] += qz * v.x;  acc[11] += qz * v.y;  acc[12] += qz * v.z;
    }

    // reduce over 4 slices: every lane ends with the full sum for its w
#pragma unroll
    for (int l = 0; l < NL; ++l) {
        acc[l] += __shfl_xor_sync(0xffffffffu, acc[l], 8);
        acc[l] += __shfl_xor_sync(0xffffffffu, acc[l], 16);
    }

    float* dst = &swout[(size_t)atom * SWLEN];
    if (lane < 8) {
        dst[lane]      = acc[0];
        dst[8  + lane] = acc[1];
        dst[16 + lane] = acc[2];
        dst[24 + lane] = acc[3];
    }

    // Gram of rows 4..12: entries e = lane and lane+32 of the 8x8 matrix
#pragma unroll
    for (int e2 = 0; e2 < 2; ++e2) {
        const int e  = lane + e2 * 32;
        const int gw = e >> 3;
        const int gp = e & 7;
        float v = 0.f;
#pragma unroll
        for (int l = 4; l < NL; ++l) {
            float aw  = __shfl_sync(0xffffffffu, acc[l], gw);
            float awp = __shfl_sync(0xffffffffu, acc[l], gp);
            v += aw * awp;
        }
        if (gp >= gw) {
            int idx = 8*gw - (gw*(gw-1))/2 + (gp - gw);   // triangular index
            dst[32 + idx] = (gp > gw) ? 2.f * v : v;
        }
    }
}

// ---------------------------------------------------------------------------
// Kernel 2b: density via 24 hyper registers + precomputed H2 pair products.
//   dens = (s0.H0)^2 + sum_{3}(s1_l.H1)^2 + sum_{36} U2[i]*P2[i]
// ---------------------------------------------------------------------------
__global__ void __launch_bounds__(128)
k_stage2(const float* __restrict__ hyper,      // (3, 8, 128)
         const int*   __restrict__ index_para, // (13,) [0,1,1,1,2x9]
         const float* __restrict__ sw,         // (8192, 68)
         float*       __restrict__ out)        // (8192, 128)
{
    const int t = threadIdx.x;

    float H0[NWAVE], H1[NWAVE], H2[NWAVE];
#pragma unroll
    for (int w = 0; w < NWAVE; ++w) {
        H0[w] = hyper[(0*NWAVE + w)*NORBIT + t];
        H1[w] = hyper[(1*NWAVE + w)*NORBIT + t];
        H2[w] = hyper[(2*NWAVE + w)*NORBIT + t];
    }
    float P2[36];
    {
        int k = 0;
#pragma unroll
        for (int w = 0; w < NWAVE; ++w)
#pragma unroll
            for (int wp = w; wp < NWAVE; ++wp)
                P2[k++] = H2[w] * H2[wp];
    }

    __shared__ float swsm[GATOMS * SWLEN];
    const int base = blockIdx.x * GATOMS;

    for (int i = t; i < GATOMS * SWLEN; i += 128)
        swsm[i] = sw[(size_t)base * SWLEN + i];
    __syncthreads();

#pragma unroll 2
    for (int g = 0; g < GATOMS; ++g) {
        const float* s = &swsm[g * SWLEN];

        float h0 = 0.f;
#pragma unroll
        for (int w = 0; w < NWAVE; ++w) h0 += s[w] * H0[w];
        float dens = h0 * h0;

#pragma unroll
        for (int l = 0; l < 3; ++l) {
            float h = 0.f;
#pragma unroll
            for (int w = 0; w < NWAVE; ++w) h += s[8 + l*NWAVE + w] * H1[w];
            dens += h * h;
        }

        float dg = 0.f;
#pragma unroll
        for (int i = 0; i < 36; ++i) dg += s[32 + i] * P2[i];
        dens += dg;

        out[(size_t)(base + g)*NORBIT + t] = dens;
    }
}

// ---------------------------------------------------------------------------
extern "C" void kernel_launch(void* const* d_in, const int* in_sizes, int n_in,
                              void* d_out, int out_size)
{
    const float* cart    = (const float*)d_in[0];
    const int*   species = (const int*)  d_in[2];
    const int*   aidx    = (const int*)  d_in[3];
    const float* shifts  = (const float*)d_in[4];
    const float* rs      = (const float*)d_in[5];
    const float* inta    = (const float*)d_in[6];
    const float* params  = (const float*)d_in[7];
    const float* hyper   = (const float*)d_in[8];
    const int*   ipara   = (const int*)  d_in[9];
    const float* cutoff  = (const float*)d_in[10];
    float*       out     = (float*)d_out;

    void* swp = nullptr;
    cudaGetSymbolAddress(&swp, d_sw);

    dim3 pgrid(PBLK, NBATCH);
    k_pairs<<<pgrid, 256>>>(cart, species, aidx, shifts);
    k_accum<<<TOTATOM / AW, 256>>>(rs, inta, params, cutoff, (float*)swp);
    k_stage2<<<TOTATOM / GATOMS, 128>>>(hyper, ipara, (const float*)swp, out);
}

// round 12
// speedup vs baseline: 1.3052x; 1.0266x over previous
#include <cuda_runtime.h>
#include <math.h>

#define NBATCH  16
#define NATOM   512
#define NEIGH   64
#define NPAIR   (NATOM*NEIGH)        /* 32768  */
#define TOTATOM (NBATCH*NATOM)       /* 8192   */
#define NPTOT   (NBATCH*NPAIR)       /* 524288 */
#define NWAVE   8
#define NL      13
#define NORBIT  128
#define GATOMS  16
#define SWLEN   68                   /* s0[8] + s1[24] + U2[36] */

#define PBLK    32                   /* k_pairs blocks per batch            */
#define PPB     1024                 /* pairs per k_pairs block             */
#define PTHR    512                  /* k_pairs threads per block           */
#define SLOT    16                   /* slots per (atom, block) cell        */
#define RCAP    128                  /* SMEM record capacity per atom       */
#define AW      8                    /* atoms (warps) per k_accum block     */

// d_rec[((b*NATOM + atom)*PBLK + blk)*SLOT + slot] : (dx,dy,dz,species)
__device__ float4        d_rec[(size_t)TOTATOM * PBLK * SLOT];
__device__ unsigned char d_cnt[TOTATOM * PBLK];   // written wholesale each run
__device__ float         d_sw[(size_t)TOTATOM * SWLEN];

// ---------------------------------------------------------------------------
// Kernel 1: displacement + species, binned via SMEM cursors (no global RMW).
// 512 threads / 2 pairs each: same grid (prologue amortized), 2x resident warps.
// ---------------------------------------------------------------------------
__global__ void __launch_bounds__(PTHR)
k_pairs(const float* __restrict__ cart,
        const int*   __restrict__ species,
        const int*   __restrict__ atom_index,
        const float* __restrict__ shifts)
{
    __shared__ float scart[NATOM * 3];
    __shared__ int   ssp  [NATOM];
    __shared__ int   scur [NATOM];

    const int blk = blockIdx.x;               // 0..31 within batch
    const int b   = blockIdx.y;
    const int tid = threadIdx.x;

    const float* cb = cart + (size_t)b * NATOM * 3;
    for (int i = tid; i < NATOM * 3; i += PTHR) scart[i] = cb[i];
    for (int i = tid; i < NATOM;     i += PTHR) {
        ssp[i]  = species[b * NATOM + i];
        scur[i] = 0;
    }
    __syncthreads();

#pragma unroll
    for (int u = 0; u < 2; ++u) {
        const int p_loc = blk * PPB + u * PTHR + tid;
        const int p     = b * NPAIR + p_loc;

        const int i_loc = atom_index[p];
        const int j_loc = atom_index[NPTOT + p];

        float dx = scart[3*i_loc+0] - scart[3*j_loc+0] + shifts[3*p+0];
        float dy = scart[3*i_loc+1] - scart[3*j_loc+1] + shifts[3*p+1];
        float dz = scart[3*i_loc+2] - scart[3*j_loc+2] + shifts[3*p+2];

        int pos = atomicAdd(&scur[i_loc], 1);     // SMEM atomic
        if (pos < SLOT)
            d_rec[(((size_t)(b * NATOM + i_loc)) * PBLK + blk) * SLOT + pos] =
                make_float4(dx, dy, dz, __int_as_float(ssp[j_loc]));
    }
    __syncthreads();

    for (int i = tid; i < NATOM; i += PTHR) {
        int c = scur[i];
        d_cnt[(b * NATOM + i) * PBLK + blk] =
            (unsigned char)(c < SLOT ? c : SLOT);
    }
}

// ---------------------------------------------------------------------------
// Kernel 2a: WARP per atom. Emits per-atom descriptor:
//   [0:8) s0 | [8:32) s1[3][8] | [32:68) U2 Gram (off-diag pre-x2)
// ---------------------------------------------------------------------------
__global__ void __launch_bounds__(256)
k_accum(const float* __restrict__ rs,
        const float* __restrict__ inta,
        const float* __restrict__ params,
        const float* __restrict__ cutoff,
        float*       __restrict__ swout)
{
    __shared__ float4 recs[AW][RCAP];
    __shared__ float2 dfc [AW][RCAP];
    __shared__ float  stab[96];       // [0:32) rs, [32:64) inta, [64:96) params

    const int t    = threadIdx.x;
    const int warp = t >> 5;
    const int lane = t & 31;
    const int atom = blockIdx.x * AW + warp;

    if (t < 32) {
        stab[t]      = rs[t];
        stab[32 + t] = inta[t];
        stab[64 + t] = params[t];
    }
    __syncthreads();                              // the only block barrier

    const float4* src = &d_rec[(size_t)atom * PBLK * SLOT];

    // counts + exclusive scan (lane = cell)
    int c = (int)d_cnt[atom * PBLK + lane];       // 32 uchars: 1 sector
    int x = c;
#pragma unroll
    for (int dd = 1; dd < 32; dd <<= 1) {
        int y = __shfl_up_sync(0xffffffffu, x, dd);
        if (lane >= dd) x += y;
    }
    const int off  = x - c;
    const int ntot = __shfl_sync(0xffffffffu, x, 31);
    const int n    = ntot < RCAP ? ntot : RCAP;

    // gather, parallel pass: 4 lanes per cell, 8 cells per iteration
#pragma unroll
    for (int it = 0; it < 4; ++it) {
        const int r  = it * 8 + (lane >> 2);
        const int s  = lane & 3;
        const int cr = __shfl_sync(0xffffffffu, c,   r);
        const int orr= __shfl_sync(0xffffffffu, off, r);
        if (s < cr && orr + s < RCAP)
            recs[warp][orr + s] = src[r * SLOT + s];
    }
    for (int s = 4; s < c; ++s)                   // rare remainder
        if (off + s < RCAP)
            recs[warp][off + s] = src[lane * SLOT + s];
    __syncwarp();

    // Phase A: per-pair distance + cutoff
    const float icp = 3.14159265358979323846f / cutoff[0];
    for (int p = lane; p < n; p += 32) {
        float4 v = recs[warp][p];
        float d  = sqrtf(v.x*v.x + v.y*v.y + v.z*v.z);
        float cc = 0.5f * __cosf(d * icp) + 0.5f;
        dfc[warp][p] = make_float2(d, cc * cc);
    }
    __syncwarp();

    // Phase B: lane = (w = lane&7, slice = lane>>3 in 0..3), unrolled x2
    const int w  = lane & 7;
    const int sl = lane >> 3;

    float acc[NL];
#pragma unroll
    for (int l = 0; l < NL; ++l) acc[l] = 0.f;

    const float rsw = stab[0];        // dummy to keep compiler from reloading
    (void)rsw;

    int p = sl;
    for (; p + 4 < n; p += 8) {
        float4 v0  = recs[warp][p];
        float2 df0 = dfc[warp][p];
        float4 v1  = recs[warp][p + 4];
        float2 df1 = dfc[warp][p + 4];
        int   sp0  = __float_as_int(v0.w);
        int   sp1  = __float_as_int(v1.w);
        float tt0  = df0.x - stab[sp0*8 + w];
        float tt1  = df1.x - stab[sp1*8 + w];
        float r0   = stab[64 + sp0*8 + w] * __expf(stab[32 + sp0*8 + w] * tt0 * tt0);
        float r1   = stab[64 + sp1*8 + w] * __expf(stab[32 + sp1*8 + w] * tt1 * tt1);
        float q0   = df0.y * r0;
        float q1   = df1.y * r1;
        float qx0 = q0*v0.x, qy0 = q0*v0.y, qz0 = q0*v0.z;
        float qx1 = q1*v1.x, qy1 = q1*v1.y, qz1 = q1*v1.z;
        acc[0]  += q0 + q1;
        acc[1]  += qx0 + qx1;      acc[2]  += qy0 + qy1;      acc[3]  += qz0 + qz1;
        acc[4]  += qx0*v0.x + qx1*v1.x;
        acc[5]  += qx0*v0.y + qx1*v1.y;
        acc[6]  += qx0*v0.z + qx1*v1.z;
        acc[7]  += qy0*v0.x + qy1*v1.x;
        acc[8]  += qy0*v0.y + qy1*v1.y;
        acc[9]  += qy0*v0.z + qy1*v1.z;
        acc[10] += qz0*v0.x + qz1*v1.x;
        acc[11] += qz0*v0.y + qz1*v1.y;
        acc[12] += qz0*v0.z + qz1*v1.z;
    }
    for (; p < n; p += 4) {
        float4 v  = recs[warp][p];
        float2 df = dfc[warp][p];
        int   sp  = __float_as_int(v.w);
        float tt  = df.x - stab[sp*8 + w];
        float r   = stab[64 + sp*8 + w] * __expf(stab[32 + sp*8 + w] * tt * tt);
        float q   = df.y * r;
        float qx = q * v.x, qy = q * v.y, qz = q * v.z;
        acc[0]  += q;
        acc[1]  += qx;        acc[2]  += qy;        acc[3]  += qz;
        acc[4]  += qx * v.x;  acc[5]  += qx * v.y;  acc[6]  += qx * v.z;
        acc[7]  += qy * v.x;  acc[8]  += qy * v.y;  acc[9]  += qy * v.z;
        acc[10] += qz * v.x;  acc[11] += qz * v.y;  acc[12] += qz * v.z;
    }

    // reduce over 4 slices: every lane ends with the full sum for its w
#pragma unroll
    for (int l = 0; l < NL; ++l) {
        acc[l] += __shfl_xor_sync(0xffffffffu, acc[l], 8);
        acc[l] += __shfl_xor_sync(0xffffffffu, acc[l], 16);
    }

    float* dst = &swout[(size_t)atom * SWLEN];
    if (lane < 8) {
        dst[lane]      = acc[0];
        dst[8  + lane] = acc[1];
        dst[16 + lane] = acc[2];
        dst[24 + lane] = acc[3];
    }

    // Gram of rows 4..12: entries e = lane and lane+32 of the 8x8 matrix
#pragma unroll
    for (int e2 = 0; e2 < 2; ++e2) {
        const int e  = lane + e2 * 32;
        const int gw = e >> 3;
        const int gp = e & 7;
        float v = 0.f;
#pragma unroll
        for (int l = 4; l < NL; ++l) {
            float aw  = __shfl_sync(0xffffffffu, acc[l], gw);
            float awp = __shfl_sync(0xffffffffu, acc[l], gp);
            v += aw * awp;
        }
        if (gp >= gw) {
            int idx = 8*gw - (gw*(gw-1))/2 + (gp - gw);   // triangular index
            dst[32 + idx] = (gp > gw) ? 2.f * v : v;
        }
    }
}

// ---------------------------------------------------------------------------
// Kernel 2b: density via 24 hyper registers + precomputed H2 pair products.
// ---------------------------------------------------------------------------
__global__ void __launch_bounds__(128)
k_stage2(const float* __restrict__ hyper,      // (3, 8, 128)
         const int*   __restrict__ index_para, // (13,) [0,1,1,1,2x9]
         const float* __restrict__ sw,         // (8192, 68)
         float*       __restrict__ out)        // (8192, 128)
{
    const int t = threadIdx.x;

    float H0[NWAVE], H1[NWAVE], H2[NWAVE];
#pragma unroll
    for (int w = 0; w < NWAVE; ++w) {
        H0[w] = hyper[(0*NWAVE + w)*NORBIT + t];
        H1[w] = hyper[(1*NWAVE + w)*NORBIT + t];
        H2[w] = hyper[(2*NWAVE + w)*NORBIT + t];
    }
    float P2[36];
    {
        int k = 0;
#pragma unroll
        for (int w = 0; w < NWAVE; ++w)
#pragma unroll
            for (int wp = w; wp < NWAVE; ++wp)
                P2[k++] = H2[w] * H2[wp];
    }

    __shared__ float swsm[GATOMS * SWLEN];
    const int base = blockIdx.x * GATOMS;

    for (int i = t; i < GATOMS * SWLEN; i += 128)
        swsm[i] = sw[(size_t)base * SWLEN + i];
    __syncthreads();

#pragma unroll 2
    for (int g = 0; g < GATOMS; ++g) {
        const float* s = &swsm[g * SWLEN];

        float h0 = 0.f;
#pragma unroll
        for (int w = 0; w < NWAVE; ++w) h0 += s[w] * H0[w];
        float dens = h0 * h0;

#pragma unroll
        for (int l = 0; l < 3; ++l) {
            float h = 0.f;
#pragma unroll
            for (int w = 0; w < NWAVE; ++w) h += s[8 + l*NWAVE + w] * H1[w];
            dens += h * h;
        }

        float dg = 0.f;
#pragma unroll
        for (int i = 0; i < 36; ++i) dg += s[32 + i] * P2[i];
        dens += dg;

        out[(size_t)(base + g)*NORBIT + t] = dens;
    }
}

// ---------------------------------------------------------------------------
extern "C" void kernel_launch(void* const* d_in, const int* in_sizes, int n_in,
                              void* d_out, int out_size)
{
    const float* cart    = (const float*)d_in[0];
    const int*   species = (const int*)  d_in[2];
    const int*   aidx    = (const int*)  d_in[3];
    const float* shifts  = (const float*)d_in[4];
    const float* rs      = (const float*)d_in[5];
    const float* inta    = (const float*)d_in[6];
    const float* params  = (const float*)d_in[7];
    const float* hyper   = (const float*)d_in[8];
    const int*   ipara   = (const int*)  d_in[9];
    const float* cutoff  = (const float*)d_in[10];
    float*       out     = (float*)d_out;

    void* swp = nullptr;
    cudaGetSymbolAddress(&swp, d_sw);

    dim3 pgrid(PBLK, NBATCH);
    k_pairs<<<pgrid, PTHR>>>(cart, species, aidx, shifts);
    k_accum<<<TOTATOM / AW, 256>>>(rs, inta, params, cutoff, (float*)swp);
    k_stage2<<<TOTATOM / GATOMS, 128>>>(hyper, ipara, (const float*)swp, out);
}